// round 12
// baseline (speedup 1.0000x reference)
#include <cuda_runtime.h>
#include <cuda_fp16.h>
#include <math.h>
#include <stdint.h>

#define BBATCH 2
#define SSEQ 2048
#define EEMB 1024
#define HHEADS 16
#define DKK 64
#define BHS (BBATCH*HHEADS*SSEQ)

// Scratch (all fp16, fragment-interleaved for single-LDS.128 operand fetch)
__device__ unsigned short g_xi[4096*1024];    // x: [m>>7][k>>6][(g*4+ks)32][lane32][comp4] b32 words
__device__ unsigned short g_wi[3][1024*1024]; // W: [n>>7][k>>6][(ng*2+sp)32][lane32][comp4]
__device__ unsigned short g_k[BHS*DKK];       // K: [bh][tile64][(ng*2+sp)16][lane32][comp4]
__device__ unsigned short g_v[BHS*DKK];       // V: [bh][tile64][(dn*2+kcp)16][lane32][comp4]
__device__ unsigned short g_q[BHS*DKK];       // Q: natural [bh][s][d]  (carries 0.125*log2e)

// ---------------- helpers ----------------
__device__ __forceinline__ void mma16(float* d, uint32_t a0, uint32_t a1,
                                      uint32_t a2, uint32_t a3,
                                      uint32_t b0, uint32_t b1)
{
    asm volatile("mma.sync.aligned.m16n8k16.row.col.f32.f16.f16.f32 "
        "{%0,%1,%2,%3}, {%4,%5,%6,%7}, {%8,%9}, {%0,%1,%2,%3};"
        : "+f"(d[0]), "+f"(d[1]), "+f"(d[2]), "+f"(d[3])
        : "r"(a0), "r"(a1), "r"(a2), "r"(a3), "r"(b0), "r"(b1));
}
__device__ __forceinline__ void mma16v(float* d, const uint4& a, uint32_t b0, uint32_t b1){
    mma16(d, a.x, a.y, a.z, a.w, b0, b1);
}
__device__ __forceinline__ float ex2f(float x){
    float r; asm("ex2.approx.f32 %0, %1;" : "=f"(r) : "f"(x)); return r;
}
__device__ __forceinline__ uint32_t packh2(float a, float b){
    __half2 h = __floats2half2_rn(a, b);
    return *(uint32_t*)&h;
}
__device__ __forceinline__ uint32_t smem_u32(const void* p){
    uint32_t a;
    asm("{ .reg .u64 t; cvta.to.shared.u64 t, %1; cvt.u32.u64 %0, t; }" : "=r"(a) : "l"(p));
    return a;
}

#define MBAR_INIT(a, c) asm volatile("mbarrier.init.shared.b64 [%0], %1;" :: "r"(a), "r"(c) : "memory")
#define MBAR_EXPECT(a, bytes) \
    asm volatile("mbarrier.arrive.expect_tx.shared.b64 _, [%0], %1;" :: "r"(a), "r"(bytes) : "memory")
#define BULK_G2S(dst, src, bytes, mbar) \
    asm volatile("cp.async.bulk.shared::cta.global.mbarrier::complete_tx::bytes [%0], [%1], %2, [%3];" \
        :: "r"(dst), "l"(src), "r"(bytes), "r"(mbar) : "memory")

#define MBAR_WAIT(mbar, par) do {                                            \
    uint32_t _m = (mbar); uint32_t _p = (par); uint32_t _done;               \
    asm volatile("{ .reg .pred p; mbarrier.try_wait.parity.acquire.cta.shared::cta.b64 p, [%1], %2; selp.b32 %0,1,0,p; }" \
        : "=r"(_done) : "r"(_m), "r"(_p) : "memory");                        \
    if (!_done) {                                                            \
        asm volatile("{ .reg .pred P1; WL%=: mbarrier.try_wait.parity.acquire.cta.shared::cta.b64 P1, [%0], %1, 0x989680; @P1 bra.uni WD%=; bra.uni WL%=; WD%=: }" \
            :: "r"(_m), "r"(_p) : "memory");                                 \
    }                                                                        \
} while(0)

// =====================================================================
// Prep: fp16-round + fragment-interleave x and W. (unchanged from R11)
// =====================================================================
__global__ __launch_bounds__(256)
void prep_kernel(const float* __restrict__ x, const float* __restrict__ Wk,
                 const float* __restrict__ Wv, const float* __restrict__ Wq)
{
    const int gi = blockIdx.x * 256 + threadIdx.x;
    if (blockIdx.y == 0) {
        if (gi < 4096*1024/4) {
            int m = gi >> 8, j = gi & 255;           // k = 4j..4j+3
            float4 v = ((const float4*)x)[gi];
            int rb = m >> 7, ch = j >> 4;
            int g = (m >> 4) & 7, ks = (j >> 2) & 3;
            int r16 = m & 15, gid = r16 & 7, rh = r16 >> 3;
            int k16 = (4 * j) & 15, tig = (k16 & 7) >> 1, khalf = k16 >> 3;
            int word = (((rb * 16 + ch) * 32) + g * 4 + ks) * 128
                     + (gid * 4 + tig) * 4 + (rh + 2 * khalf);
            *(__half2*)(g_xi + 2 * word)       = __floats2half2_rn(v.x, v.y);
            *(__half2*)(g_xi + 2 * (word + 4)) = __floats2half2_rn(v.z, v.w);
        }
    } else {
        if (gi < 1024*1024/4) {
            const float* W = (blockIdx.y == 1) ? Wk : (blockIdx.y == 2) ? Wv : Wq;
            unsigned short* dst = g_wi[blockIdx.y - 1];
            int n = gi >> 8, j = gi & 255;
            float4 v = ((const float4*)W)[gi];
            int nb = n >> 7, ch = j >> 4;
            int ng = (n >> 3) & 15, gid = n & 7;
            int ks = (j >> 2) & 3, sp = ks >> 1, kso = ks & 1;
            int k16 = (4 * j) & 15, tig = (k16 & 7) >> 1, khalf = k16 >> 3;
            int word = (((nb * 16 + ch) * 32) + ng * 2 + sp) * 128
                     + (gid * 4 + tig) * 4 + (kso * 2 + khalf);
            *(__half2*)(dst + 2 * word)       = __floats2half2_rn(v.x, v.y);
            *(__half2*)(dst + 2 * (word + 4)) = __floats2half2_rn(v.z, v.w);
        }
    }
}

// =====================================================================
// Merged projection: fp16 m16n8k16, 16 chunks of 64k, 3-stage bulk.
// (unchanged from R11 except Q multiplier folds log2e)
// =====================================================================
#define PJ_SMEM (98304 + 32)

__global__ __launch_bounds__(256, 2)
void proj_mma(const float* __restrict__ theta)
{
    extern __shared__ char smc[];
    const uint32_t sb = smem_u32(smc);
    const uint32_t mb0 = sb + 98304;
    const int tid = threadIdx.x;
    const int wid = tid >> 5, lane = tid & 31;
    const int gid = lane >> 2, tig = lane & 3;
    const int wm = wid >> 1, wn = wid & 1;
    const int row0 = blockIdx.y * 128;
    const int col0g = blockIdx.x * 128;
    const int mode = col0g >> 10;
    const int coll = col0g & 1023;
    const int nb = coll >> 7;

    float acc[2][8][4];
    #pragma unroll
    for (int i = 0; i < 2; i++)
        #pragma unroll
        for (int j = 0; j < 8; j++)
            #pragma unroll
            for (int e = 0; e < 4; e++) acc[i][j][e] = 0.f;

    const unsigned short* Ab = g_xi + (size_t)blockIdx.y * 131072;
    const unsigned short* Wb = g_wi[mode] + (size_t)nb * 131072;

    auto issue = [&](int ch, int b) {
        uint32_t mbar = mb0 + b * 8;
        MBAR_EXPECT(mbar, 32768u);
        BULK_G2S(sb + b * 16384,         (const void*)(Ab + ch * 8192), 16384u, mbar);
        BULK_G2S(sb + 49152 + b * 16384, (const void*)(Wb + ch * 8192), 16384u, mbar);
    };

    if (tid == 0) { MBAR_INIT(mb0, 1); MBAR_INIT(mb0 + 8, 1); MBAR_INIT(mb0 + 16, 1); }
    __syncthreads();
    if (tid == 0) { issue(0, 0); issue(1, 1); }

    int buf = 0, par = 0;
    #pragma unroll 1
    for (int ch = 0; ch < 16; ch++) {
        MBAR_WAIT(mb0 + buf * 8, par);
        __syncthreads();
        if (ch + 2 < 16 && tid == 0) {
            int nbuf = buf + 2; if (nbuf >= 3) nbuf -= 3;
            issue(ch + 2, nbuf);
        }

        const uint4* As = (const uint4*)(smc + buf * 16384);
        const uint4* Ws = (const uint4*)(smc + 49152 + buf * 16384);
        #pragma unroll
        for (int sp = 0; sp < 2; sp++) {
            uint4 af[2][2];
            #pragma unroll
            for (int tm = 0; tm < 2; tm++)
                #pragma unroll
                for (int kso = 0; kso < 2; kso++)
                    af[tm][kso] = As[((2*wm+tm)*4 + 2*sp+kso) * 32 + lane];
            #pragma unroll
            for (int tn = 0; tn < 8; tn++) {
                uint4 wb = Ws[((wn*8+tn)*2 + sp) * 32 + lane];
                #pragma unroll
                for (int tm = 0; tm < 2; tm++) {
                    mma16v(acc[tm][tn], af[tm][0], wb.x, wb.y);
                    mma16v(acc[tm][tn], af[tm][1], wb.z, wb.w);
                }
            }
        }
        if (++buf == 3) { buf = 0; par ^= 1; }
    }

    // epilogue: fp16 scatter to K/V fragment layouts, Q natural (+cos, log2e folded)
    #pragma unroll
    for (int tm = 0; tm < 2; tm++) {
        #pragma unroll
        for (int tn = 0; tn < 8; tn++) {
            #pragma unroll
            for (int e = 0; e < 4; e++) {
                int m = row0 + wm * 32 + tm * 16 + gid + (e >= 2 ? 8 : 0);
                int nn = coll + wn * 64 + tn * 8 + 2 * tig + (e & 1);
                int b = m >> 11, s = m & (SSEQ - 1);
                int h = nn >> 6, d = nn & (DKK - 1);
                int bh = b * HHEADS + h;
                float v = acc[tm][tn][e];
                size_t idx;
                if (mode == 0) {
                    int tile = s >> 6, key = s & 63;
                    int ng = key >> 3, gidk = key & 7;
                    int ks = d >> 4, sp = ks >> 1, kso = ks & 1;
                    int k16 = d & 15, khalf = k16 >> 3, tigk = (k16 & 7) >> 1, kodd = d & 1;
                    int word = ((ng * 2 + sp) * 32 + gidk * 4 + tigk) * 4 + (kso * 2 + khalf);
                    idx = ((size_t)(bh * 32 + tile) * 2048 + word) * 2 + kodd;
                } else if (mode == 1) {
                    int tile = s >> 6, key = s & 63;
                    int dn = d >> 3, gidd = d & 7;
                    int kc = key >> 4, kcp = kc >> 1, kco = kc & 1;
                    int key16 = key & 15, khalf = key16 >> 3, tigv = (key16 & 7) >> 1, kodd = key & 1;
                    int word = ((dn * 2 + kcp) * 32 + gidd * 4 + tigv) * 4 + (kco * 2 + khalf);
                    idx = ((size_t)(bh * 32 + tile) * 2048 + word) * 2 + kodd;
                } else {
                    v = cosf(v + __ldg(&theta[d])) * 0.18033688011112042f; // 0.125 * log2(e)
                    idx = ((size_t)bh * SSEQ + s) * DKK + d;
                }
                unsigned short* dst = (mode == 0) ? g_k : (mode == 1) ? g_v : g_q;
                __half hv = __float2half_rn(v);
                dst[idx] = *(unsigned short*)&hv;
            }
        }
    }
}

// =====================================================================
// Attention: CTA = 256q x 1 head, 8 warps, warp = 32q x 64keys x 64d.
// Cross-tile software pipeline: exp(t) | S(t+1) | PV(t) per iteration,
// so the tensor pipe gets 128 back-to-back mma while MUFU drains.
// p = ex2(S) with log2e pre-folded into Q. 3-stage bulk-copy.
// smem bytes: K[s] @ s*8192 ; V[s] @ 24576 + s*8192 ; mbars @ 49152
// =====================================================================
#define AT_SMEM (49152 + 32)

__global__ __launch_bounds__(256, 1)
void attn_mma(float* __restrict__ out)
{
    extern __shared__ char smc[];
    const uint32_t sb = smem_u32(smc);
    const uint32_t mb0 = sb + 49152;
    const int tid = threadIdx.x;
    const int wid = tid >> 5, lane = tid & 31;
    const int gid = lane >> 2, tig = lane & 3;
    const int bh = blockIdx.y;
    const int s0 = blockIdx.x * 256;

    // ---- Q fragments in registers: 2 m-groups x 4 k-steps ----
    uint4 qf[2][4];
    #pragma unroll
    for (int mg = 0; mg < 2; mg++) {
        const unsigned short* qb = g_q + ((size_t)bh * SSEQ + s0 + wid * 32 + mg * 16) * DKK;
        #pragma unroll
        for (int ks = 0; ks < 4; ks++) {
            int c = 16 * ks + 2 * tig;
            qf[mg][ks].x = *(const uint32_t*)(qb + gid * DKK + c);
            qf[mg][ks].y = *(const uint32_t*)(qb + (gid + 8) * DKK + c);
            qf[mg][ks].z = *(const uint32_t*)(qb + gid * DKK + c + 8);
            qf[mg][ks].w = *(const uint32_t*)(qb + (gid + 8) * DKK + c + 8);
        }
    }

    const unsigned short* kg = g_k + (size_t)bh * 131072;
    const unsigned short* vg = g_v + (size_t)bh * 131072;

    auto issue = [&](int t, int b) {
        uint32_t mbar = mb0 + b * 8;
        MBAR_EXPECT(mbar, 16384u);
        BULK_G2S(sb + b * 8192,         (const void*)(kg + t * 4096), 8192u, mbar);
        BULK_G2S(sb + 24576 + b * 8192, (const void*)(vg + t * 4096), 8192u, mbar);
    };

    float oacc[2][8][4];
    #pragma unroll
    for (int mg = 0; mg < 2; mg++)
        #pragma unroll
        for (int dn = 0; dn < 8; dn++)
            #pragma unroll
            for (int e = 0; e < 4; e++) oacc[mg][dn][e] = 0.f;
    float lsum[2][2] = {{0.f, 0.f}, {0.f, 0.f}};

    if (tid == 0) { MBAR_INIT(mb0, 1); MBAR_INIT(mb0 + 8, 1); MBAR_INIT(mb0 + 16, 1); }
    __syncthreads();
    if (tid == 0) { issue(0, 0); issue(1, 1); }

    // ---- S-GEMM helper: compute sacc for tile in buffer kb ----
    float sacc[2][8][4];
    auto s_gemm = [&](const uint4* Kp) {
        #pragma unroll
        for (int mg = 0; mg < 2; mg++)
            #pragma unroll
            for (int tn = 0; tn < 8; tn++)
                #pragma unroll
                for (int e = 0; e < 4; e++) sacc[mg][tn][e] = 0.f;
        #pragma unroll
        for (int sp = 0; sp < 2; sp++) {
            #pragma unroll
            for (int tn = 0; tn < 8; tn++) {
                uint4 kb = Kp[(tn * 2 + sp) * 32 + lane];
                #pragma unroll
                for (int mg = 0; mg < 2; mg++) {
                    mma16v(sacc[mg][tn], qf[mg][2 * sp    ], kb.x, kb.y);
                    mma16v(sacc[mg][tn], qf[mg][2 * sp + 1], kb.z, kb.w);
                }
            }
        }
    };

    // Prologue: wait tile 0, compute S(0)
    MBAR_WAIT(mb0, 0);
    __syncthreads();
    s_gemm((const uint4*)(smc));

    #pragma unroll 1
    for (int u = 0; u < 32; u++) {
        // ---- p = ex2(S(u)) (log2e folded into Q), row sums, pack fp16 ----
        uint32_t plo[2][8], phi[2][8];
        #pragma unroll
        for (int mg = 0; mg < 2; mg++)
            #pragma unroll
            for (int tn = 0; tn < 8; tn++) {
                float p0 = ex2f(sacc[mg][tn][0]);
                float p1 = ex2f(sacc[mg][tn][1]);
                float p2 = ex2f(sacc[mg][tn][2]);
                float p3 = ex2f(sacc[mg][tn][3]);
                lsum[mg][0] += p0 + p1;
                lsum[mg][1] += p2 + p3;
                plo[mg][tn] = packh2(p0, p1);
                phi[mg][tn] = packh2(p2, p3);
            }

        // ---- wait K(u+1), refill pipeline, S(u+1) (overlaps exp/PV) ----
        if (u < 32 - 1) {
            int n = u + 1;
            int b = n - (n / 3) * 3;
            int parn = (n / 3) & 1;
            MBAR_WAIT(mb0 + b * 8, parn);
            __syncthreads();            // all reads of buffer (u+2)%3's old tile are done
            if (u + 2 < 32 && tid == 0) {
                int nb2 = u + 2;
                issue(nb2, nb2 - (nb2 / 3) * 3);
            }
            s_gemm((const uint4*)(smc + b * 8192));
        }

        // ---- O += P(u) @ V(u) ----
        const int vb = u - (u / 3) * 3;
        const uint4* Vp = (const uint4*)(smc + 24576 + vb * 8192);
        #pragma unroll
        for (int kcp = 0; kcp < 2; kcp++) {
            #pragma unroll
            for (int dn = 0; dn < 8; dn++) {
                uint4 vv = Vp[(dn * 2 + kcp) * 32 + lane];
                #pragma unroll
                for (int mg = 0; mg < 2; mg++) {
                    mma16(oacc[mg][dn],
                          plo[mg][4*kcp    ], phi[mg][4*kcp    ],
                          plo[mg][4*kcp + 1], phi[mg][4*kcp + 1],
                          vv.x, vv.y);
                    mma16(oacc[mg][dn],
                          plo[mg][4*kcp + 2], phi[mg][4*kcp + 2],
                          plo[mg][4*kcp + 3], phi[mg][4*kcp + 3],
                          vv.z, vv.w);
                }
            }
        }
    }

    // ---- finalize l (quad reduce) and write out ----
    #pragma unroll
    for (int mg = 0; mg < 2; mg++)
        #pragma unroll
        for (int r = 0; r < 2; r++) {
            lsum[mg][r] += __shfl_xor_sync(0xffffffffu, lsum[mg][r], 1);
            lsum[mg][r] += __shfl_xor_sync(0xffffffffu, lsum[mg][r], 2);
        }

    const int b = bh >> 4, h = bh & (HHEADS - 1);
    #pragma unroll
    for (int mg = 0; mg < 2; mg++) {
        const float inv0 = 1.f / lsum[mg][0];
        const float inv1 = 1.f / lsum[mg][1];
        float* o0 = out + ((size_t)b * SSEQ + s0 + wid * 32 + mg * 16 + gid) * EEMB + h * DKK;
        float* o1 = o0 + 8 * EEMB;
        #pragma unroll
        for (int dn = 0; dn < 8; dn++) {
            int c = dn * 8 + 2 * tig;
            *(float2*)(o0 + c) = make_float2(oacc[mg][dn][0] * inv0, oacc[mg][dn][1] * inv0);
            *(float2*)(o1 + c) = make_float2(oacc[mg][dn][2] * inv1, oacc[mg][dn][3] * inv1);
        }
    }
}

// ===================== launch =====================
extern "C" void kernel_launch(void* const* d_in, const int* in_sizes, int n_in,
                              void* d_out, int out_size)
{
    const float* x     = (const float*)d_in[0];
    const float* Wk    = (const float*)d_in[1];
    const float* Wv    = (const float*)d_in[2];
    const float* Wq    = (const float*)d_in[3];
    const float* theta = (const float*)d_in[4];
    float* out = (float*)d_out;

    cudaFuncSetAttribute(proj_mma, cudaFuncAttributeMaxDynamicSharedMemorySize, PJ_SMEM);
    cudaFuncSetAttribute(attn_mma, cudaFuncAttributeMaxDynamicSharedMemorySize, AT_SMEM);

    prep_kernel<<<dim3(4096, 4), 256>>>(x, Wk, Wv, Wq);

    dim3 gp(3 * EEMB / 128, (BBATCH * SSEQ) / 128);   // (24, 32)
    proj_mma<<<gp, 256, PJ_SMEM>>>(theta);

    dim3 ga(SSEQ / 256, BBATCH * HHEADS);              // (8, 32)
    attn_mma<<<ga, 256, AT_SMEM>>>(out);
}

// round 13
// speedup vs baseline: 1.2042x; 1.2042x over previous
#include <cuda_runtime.h>
#include <cuda_fp16.h>
#include <math.h>
#include <stdint.h>

#define BBATCH 2
#define SSEQ 2048
#define EEMB 1024
#define HHEADS 16
#define DKK 64
#define BHS (BBATCH*HHEADS*SSEQ)

// Scratch (all fp16, fragment-interleaved for single-LDS.128 operand fetch)
__device__ unsigned short g_xi[4096*1024];    // x: [m>>7][k>>6][(g*4+ks)32][lane32][comp4] b32 words
__device__ unsigned short g_wi[3][1024*1024]; // W: [n>>7][k>>6][(ng*2+sp)32][lane32][comp4]
__device__ unsigned short g_k[BHS*DKK];       // K: [bh][tile64][(ng*2+sp)16][lane32][comp4]
__device__ unsigned short g_v[BHS*DKK];       // V: [bh][tile64][(dn*2+kcp)16][lane32][comp4]
__device__ unsigned short g_q[BHS*DKK];       // Q: natural [bh][s][d]  (carries 0.125*log2e)

// ---------------- helpers ----------------
__device__ __forceinline__ void mma16(float* d, uint32_t a0, uint32_t a1,
                                      uint32_t a2, uint32_t a3,
                                      uint32_t b0, uint32_t b1)
{
    asm volatile("mma.sync.aligned.m16n8k16.row.col.f32.f16.f16.f32 "
        "{%0,%1,%2,%3}, {%4,%5,%6,%7}, {%8,%9}, {%0,%1,%2,%3};"
        : "+f"(d[0]), "+f"(d[1]), "+f"(d[2]), "+f"(d[3])
        : "r"(a0), "r"(a1), "r"(a2), "r"(a3), "r"(b0), "r"(b1));
}
__device__ __forceinline__ void mma16v(float* d, const uint4& a, uint32_t b0, uint32_t b1){
    mma16(d, a.x, a.y, a.z, a.w, b0, b1);
}
__device__ __forceinline__ float ex2f(float x){
    float r; asm("ex2.approx.f32 %0, %1;" : "=f"(r) : "f"(x)); return r;
}
__device__ __forceinline__ uint32_t packh2(float a, float b){
    __half2 h = __floats2half2_rn(a, b);
    return *(uint32_t*)&h;
}
__device__ __forceinline__ uint32_t smem_u32(const void* p){
    uint32_t a;
    asm("{ .reg .u64 t; cvta.to.shared.u64 t, %1; cvt.u32.u64 %0, t; }" : "=r"(a) : "l"(p));
    return a;
}

#define MBAR_INIT(a, c) asm volatile("mbarrier.init.shared.b64 [%0], %1;" :: "r"(a), "r"(c) : "memory")
#define MBAR_EXPECT(a, bytes) \
    asm volatile("mbarrier.arrive.expect_tx.shared.b64 _, [%0], %1;" :: "r"(a), "r"(bytes) : "memory")
#define BULK_G2S(dst, src, bytes, mbar) \
    asm volatile("cp.async.bulk.shared::cta.global.mbarrier::complete_tx::bytes [%0], [%1], %2, [%3];" \
        :: "r"(dst), "l"(src), "r"(bytes), "r"(mbar) : "memory")

#define MBAR_WAIT(mbar, par) do {                                            \
    uint32_t _m = (mbar); uint32_t _p = (par); uint32_t _done;               \
    asm volatile("{ .reg .pred p; mbarrier.try_wait.parity.acquire.cta.shared::cta.b64 p, [%1], %2; selp.b32 %0,1,0,p; }" \
        : "=r"(_done) : "r"(_m), "r"(_p) : "memory");                        \
    if (!_done) {                                                            \
        asm volatile("{ .reg .pred P1; WL%=: mbarrier.try_wait.parity.acquire.cta.shared::cta.b64 P1, [%0], %1, 0x989680; @P1 bra.uni WD%=; bra.uni WL%=; WD%=: }" \
            :: "r"(_m), "r"(_p) : "memory");                                 \
    }                                                                        \
} while(0)

// =====================================================================
// Prep: fp16-round + fragment-interleave x and W. (unchanged from R11)
// =====================================================================
__global__ __launch_bounds__(256)
void prep_kernel(const float* __restrict__ x, const float* __restrict__ Wk,
                 const float* __restrict__ Wv, const float* __restrict__ Wq)
{
    const int gi = blockIdx.x * 256 + threadIdx.x;
    if (blockIdx.y == 0) {
        if (gi < 4096*1024/4) {
            int m = gi >> 8, j = gi & 255;           // k = 4j..4j+3
            float4 v = ((const float4*)x)[gi];
            int rb = m >> 7, ch = j >> 4;
            int g = (m >> 4) & 7, ks = (j >> 2) & 3;
            int r16 = m & 15, gid = r16 & 7, rh = r16 >> 3;
            int k16 = (4 * j) & 15, tig = (k16 & 7) >> 1, khalf = k16 >> 3;
            int word = (((rb * 16 + ch) * 32) + g * 4 + ks) * 128
                     + (gid * 4 + tig) * 4 + (rh + 2 * khalf);
            *(__half2*)(g_xi + 2 * word)       = __floats2half2_rn(v.x, v.y);
            *(__half2*)(g_xi + 2 * (word + 4)) = __floats2half2_rn(v.z, v.w);
        }
    } else {
        if (gi < 1024*1024/4) {
            const float* W = (blockIdx.y == 1) ? Wk : (blockIdx.y == 2) ? Wv : Wq;
            unsigned short* dst = g_wi[blockIdx.y - 1];
            int n = gi >> 8, j = gi & 255;
            float4 v = ((const float4*)W)[gi];
            int nb = n >> 7, ch = j >> 4;
            int ng = (n >> 3) & 15, gid = n & 7;
            int ks = (j >> 2) & 3, sp = ks >> 1, kso = ks & 1;
            int k16 = (4 * j) & 15, tig = (k16 & 7) >> 1, khalf = k16 >> 3;
            int word = (((nb * 16 + ch) * 32) + ng * 2 + sp) * 128
                     + (gid * 4 + tig) * 4 + (kso * 2 + khalf);
            *(__half2*)(dst + 2 * word)       = __floats2half2_rn(v.x, v.y);
            *(__half2*)(dst + 2 * (word + 4)) = __floats2half2_rn(v.z, v.w);
        }
    }
}

// =====================================================================
// Merged projection: fp16 m16n8k16, 16 chunks of 64k, 3-stage bulk.
// Epilogue: K and Q stores PAIRED into u32 (coalesce + halve count).
// =====================================================================
#define PJ_SMEM (98304 + 32)

__global__ __launch_bounds__(256, 2)
void proj_mma(const float* __restrict__ theta)
{
    extern __shared__ char smc[];
    const uint32_t sb = smem_u32(smc);
    const uint32_t mb0 = sb + 98304;
    const int tid = threadIdx.x;
    const int wid = tid >> 5, lane = tid & 31;
    const int gid = lane >> 2, tig = lane & 3;
    const int wm = wid >> 1, wn = wid & 1;
    const int row0 = blockIdx.y * 128;
    const int col0g = blockIdx.x * 128;
    const int mode = col0g >> 10;
    const int coll = col0g & 1023;
    const int nb = coll >> 7;

    float acc[2][8][4];
    #pragma unroll
    for (int i = 0; i < 2; i++)
        #pragma unroll
        for (int j = 0; j < 8; j++)
            #pragma unroll
            for (int e = 0; e < 4; e++) acc[i][j][e] = 0.f;

    const unsigned short* Ab = g_xi + (size_t)blockIdx.y * 131072;
    const unsigned short* Wb = g_wi[mode] + (size_t)nb * 131072;

    auto issue = [&](int ch, int b) {
        uint32_t mbar = mb0 + b * 8;
        MBAR_EXPECT(mbar, 32768u);
        BULK_G2S(sb + b * 16384,         (const void*)(Ab + ch * 8192), 16384u, mbar);
        BULK_G2S(sb + 49152 + b * 16384, (const void*)(Wb + ch * 8192), 16384u, mbar);
    };

    if (tid == 0) { MBAR_INIT(mb0, 1); MBAR_INIT(mb0 + 8, 1); MBAR_INIT(mb0 + 16, 1); }
    __syncthreads();
    if (tid == 0) { issue(0, 0); issue(1, 1); }

    int buf = 0, par = 0;
    #pragma unroll 1
    for (int ch = 0; ch < 16; ch++) {
        MBAR_WAIT(mb0 + buf * 8, par);
        __syncthreads();
        if (ch + 2 < 16 && tid == 0) {
            int nbuf = buf + 2; if (nbuf >= 3) nbuf -= 3;
            issue(ch + 2, nbuf);
        }

        const uint4* As = (const uint4*)(smc + buf * 16384);
        const uint4* Ws = (const uint4*)(smc + 49152 + buf * 16384);
        #pragma unroll
        for (int sp = 0; sp < 2; sp++) {
            uint4 af[2][2];
            #pragma unroll
            for (int tm = 0; tm < 2; tm++)
                #pragma unroll
                for (int kso = 0; kso < 2; kso++)
                    af[tm][kso] = As[((2*wm+tm)*4 + 2*sp+kso) * 32 + lane];
            #pragma unroll
            for (int tn = 0; tn < 8; tn++) {
                uint4 wb = Ws[((wn*8+tn)*2 + sp) * 32 + lane];
                #pragma unroll
                for (int tm = 0; tm < 2; tm++) {
                    mma16v(acc[tm][tn], af[tm][0], wb.x, wb.y);
                    mma16v(acc[tm][tn], af[tm][1], wb.z, wb.w);
                }
            }
        }
        if (++buf == 3) { buf = 0; par ^= 1; }
    }

    // ---- epilogue ----
    #pragma unroll
    for (int tm = 0; tm < 2; tm++) {
        #pragma unroll
        for (int tn = 0; tn < 8; tn++) {
            #pragma unroll
            for (int half = 0; half < 2; half++) {       // half 0: e0,e1 (row m); half 1: e2,e3 (row m+8)
                int m = row0 + wm * 32 + tm * 16 + gid + half * 8;
                int nn = coll + wn * 64 + tn * 8 + 2 * tig;    // even; pair covers nn, nn+1
                int b = m >> 11, s = m & (SSEQ - 1);
                int h = nn >> 6, d = nn & (DKK - 1);           // d even
                int bh = b * HHEADS + h;
                float v0 = acc[tm][tn][2 * half];
                float v1 = acc[tm][tn][2 * half + 1];
                if (mode == 0) {
                    // K: d,d+1 share one b-frag u32 word (kodd = 0/1)
                    int tile = s >> 6, key = s & 63;
                    int ng = key >> 3, gidk = key & 7;
                    int ks = d >> 4, sp = ks >> 1, kso = ks & 1;
                    int k16 = d & 15, khalf = k16 >> 3, tigk = (k16 & 7) >> 1;
                    int word = ((ng * 2 + sp) * 32 + gidk * 4 + tigk) * 4 + (kso * 2 + khalf);
                    uint32_t* dst32 = (uint32_t*)g_k;
                    dst32[(size_t)(bh * 32 + tile) * 2048 + word] = packh2(v0, v1);
                } else if (mode == 1) {
                    // V: b-frag words pack KEY pairs, not d pairs -> scalar u16 stores
                    int tile = s >> 6, key = s & 63;
                    int kc = key >> 4, kcp = kc >> 1, kco = kc & 1;
                    int key16 = key & 15, khalf = key16 >> 3, tigv = (key16 & 7) >> 1, kodd = key & 1;
                    #pragma unroll
                    for (int dd = 0; dd < 2; dd++) {
                        int dcur = d + dd;
                        int dn = dcur >> 3, gidd = dcur & 7;
                        int word = ((dn * 2 + kcp) * 32 + gidd * 4 + tigv) * 4 + (kco * 2 + khalf);
                        float vv = dd ? v1 : v0;
                        __half hv = __float2half_rn(vv);
                        g_v[((size_t)(bh * 32 + tile) * 2048 + word) * 2 + kodd] = *(unsigned short*)&hv;
                    }
                } else {
                    // Q: natural layout, d and d+1 adjacent -> one u32 store (log2e folded)
                    float q0 = cosf(v0 + __ldg(&theta[d]))     * 0.18033688011112042f;
                    float q1 = cosf(v1 + __ldg(&theta[d + 1])) * 0.18033688011112042f;
                    uint32_t* dst32 = (uint32_t*)g_q;
                    dst32[(((size_t)bh * SSEQ + s) * DKK + d) >> 1] = packh2(q0, q1);
                }
            }
        }
    }
}

// =====================================================================
// Attention: R11 structure (proven). CTA = 256q x 1 head, 8 warps.
// fp16 m16n8k16; P transpose free; ex2 with log2e pre-folded in Q.
// smem bytes: K[s] @ s*8192 ; V[s] @ 24576 + s*8192 ; mbars @ 49152
// =====================================================================
#define AT_SMEM (49152 + 32)

__global__ __launch_bounds__(256, 1)
void attn_mma(float* __restrict__ out)
{
    extern __shared__ char smc[];
    const uint32_t sb = smem_u32(smc);
    const uint32_t mb0 = sb + 49152;
    const int tid = threadIdx.x;
    const int wid = tid >> 5, lane = tid & 31;
    const int gid = lane >> 2, tig = lane & 3;
    const int bh = blockIdx.y;
    const int s0 = blockIdx.x * 256;

    // ---- Q fragments in registers: 2 m-groups x 4 k-steps ----
    uint4 qf[2][4];
    #pragma unroll
    for (int mg = 0; mg < 2; mg++) {
        const unsigned short* qb = g_q + ((size_t)bh * SSEQ + s0 + wid * 32 + mg * 16) * DKK;
        #pragma unroll
        for (int ks = 0; ks < 4; ks++) {
            int c = 16 * ks + 2 * tig;
            qf[mg][ks].x = *(const uint32_t*)(qb + gid * DKK + c);
            qf[mg][ks].y = *(const uint32_t*)(qb + (gid + 8) * DKK + c);
            qf[mg][ks].z = *(const uint32_t*)(qb + gid * DKK + c + 8);
            qf[mg][ks].w = *(const uint32_t*)(qb + (gid + 8) * DKK + c + 8);
        }
    }

    const unsigned short* kg = g_k + (size_t)bh * 131072;
    const unsigned short* vg = g_v + (size_t)bh * 131072;

    auto issue = [&](int t, int b) {
        uint32_t mbar = mb0 + b * 8;
        MBAR_EXPECT(mbar, 16384u);
        BULK_G2S(sb + b * 8192,         (const void*)(kg + t * 4096), 8192u, mbar);
        BULK_G2S(sb + 24576 + b * 8192, (const void*)(vg + t * 4096), 8192u, mbar);
    };

    if (tid == 0) { MBAR_INIT(mb0, 1); MBAR_INIT(mb0 + 8, 1); MBAR_INIT(mb0 + 16, 1); }
    __syncthreads();
    if (tid == 0) { issue(0, 0); issue(1, 1); }

    float oacc[2][8][4];
    #pragma unroll
    for (int mg = 0; mg < 2; mg++)
        #pragma unroll
        for (int dn = 0; dn < 8; dn++)
            #pragma unroll
            for (int e = 0; e < 4; e++) oacc[mg][dn][e] = 0.f;
    float lsum[2][2] = {{0.f, 0.f}, {0.f, 0.f}};

    int buf = 0, par = 0;
    #pragma unroll 1
    for (int t = 0; t < 32; t++) {
        MBAR_WAIT(mb0 + buf * 8, par);
        __syncthreads();
        if (t + 2 < 32 && tid == 0) {
            int nbuf = buf + 2; if (nbuf >= 3) nbuf -= 3;
            issue(t + 2, nbuf);
        }

        const uint4* Kp = (const uint4*)(smc + buf * 8192);
        const uint4* Vp = (const uint4*)(smc + 24576 + buf * 8192);

        // ---- S = Q @ K^T ----
        float sacc[2][8][4];
        #pragma unroll
        for (int mg = 0; mg < 2; mg++)
            #pragma unroll
            for (int tn = 0; tn < 8; tn++)
                #pragma unroll
                for (int e = 0; e < 4; e++) sacc[mg][tn][e] = 0.f;

        #pragma unroll
        for (int sp = 0; sp < 2; sp++) {
            #pragma unroll
            for (int tn = 0; tn < 8; tn++) {
                uint4 kb = Kp[(tn * 2 + sp) * 32 + lane];
                #pragma unroll
                for (int mg = 0; mg < 2; mg++) {
                    mma16v(sacc[mg][tn], qf[mg][2 * sp    ], kb.x, kb.y);
                    mma16v(sacc[mg][tn], qf[mg][2 * sp + 1], kb.z, kb.w);
                }
            }
        }

        // ---- P = ex2(S) (log2e folded into Q), row sums, pack fp16 ----
        uint32_t plo[2][8], phi[2][8];
        #pragma unroll
        for (int mg = 0; mg < 2; mg++)
            #pragma unroll
            for (int tn = 0; tn < 8; tn++) {
                float p0 = ex2f(sacc[mg][tn][0]);
                float p1 = ex2f(sacc[mg][tn][1]);
                float p2 = ex2f(sacc[mg][tn][2]);
                float p3 = ex2f(sacc[mg][tn][3]);
                lsum[mg][0] += p0 + p1;
                lsum[mg][1] += p2 + p3;
                plo[mg][tn] = packh2(p0, p1);
                phi[mg][tn] = packh2(p2, p3);
            }

        // ---- O += P @ V : A-frags directly from packed S pairs ----
        #pragma unroll
        for (int kcp = 0; kcp < 2; kcp++) {
            #pragma unroll
            for (int dn = 0; dn < 8; dn++) {
                uint4 vb = Vp[(dn * 2 + kcp) * 32 + lane];
                #pragma unroll
                for (int mg = 0; mg < 2; mg++) {
                    mma16(oacc[mg][dn],
                          plo[mg][4*kcp    ], phi[mg][4*kcp    ],
                          plo[mg][4*kcp + 1], phi[mg][4*kcp + 1],
                          vb.x, vb.y);
                    mma16(oacc[mg][dn],
                          plo[mg][4*kcp + 2], phi[mg][4*kcp + 2],
                          plo[mg][4*kcp + 3], phi[mg][4*kcp + 3],
                          vb.z, vb.w);
                }
            }
        }
        if (++buf == 3) { buf = 0; par ^= 1; }
    }

    // ---- finalize l (quad reduce) and write out ----
    #pragma unroll
    for (int mg = 0; mg < 2; mg++)
        #pragma unroll
        for (int r = 0; r < 2; r++) {
            lsum[mg][r] += __shfl_xor_sync(0xffffffffu, lsum[mg][r], 1);
            lsum[mg][r] += __shfl_xor_sync(0xffffffffu, lsum[mg][r], 2);
        }

    const int b = bh >> 4, h = bh & (HHEADS - 1);
    #pragma unroll
    for (int mg = 0; mg < 2; mg++) {
        const float inv0 = 1.f / lsum[mg][0];
        const float inv1 = 1.f / lsum[mg][1];
        float* o0 = out + ((size_t)b * SSEQ + s0 + wid * 32 + mg * 16 + gid) * EEMB + h * DKK;
        float* o1 = o0 + 8 * EEMB;
        #pragma unroll
        for (int dn = 0; dn < 8; dn++) {
            int c = dn * 8 + 2 * tig;
            *(float2*)(o0 + c) = make_float2(oacc[mg][dn][0] * inv0, oacc[mg][dn][1] * inv0);
            *(float2*)(o1 + c) = make_float2(oacc[mg][dn][2] * inv1, oacc[mg][dn][3] * inv1);
        }
    }
}

// ===================== launch =====================
extern "C" void kernel_launch(void* const* d_in, const int* in_sizes, int n_in,
                              void* d_out, int out_size)
{
    const float* x     = (const float*)d_in[0];
    const float* Wk    = (const float*)d_in[1];
    const float* Wv    = (const float*)d_in[2];
    const float* Wq    = (const float*)d_in[3];
    const float* theta = (const float*)d_in[4];
    float* out = (float*)d_out;

    cudaFuncSetAttribute(proj_mma, cudaFuncAttributeMaxDynamicSharedMemorySize, PJ_SMEM);
    cudaFuncSetAttribute(attn_mma, cudaFuncAttributeMaxDynamicSharedMemorySize, AT_SMEM);

    prep_kernel<<<dim3(4096, 4), 256>>>(x, Wk, Wv, Wq);

    dim3 gp(3 * EEMB / 128, (BBATCH * SSEQ) / 128);   // (24, 32)
    proj_mma<<<gp, 256, PJ_SMEM>>>(theta);

    dim3 ga(SSEQ / 256, BBATCH * HHEADS);              // (8, 32)
    attn_mma<<<ga, 256, AT_SMEM>>>(out);
}

// round 14
// speedup vs baseline: 1.3101x; 1.0879x over previous
#include <cuda_runtime.h>
#include <cuda_fp16.h>
#include <math.h>
#include <stdint.h>

#define BBATCH 2
#define SSEQ 2048
#define EEMB 1024
#define HHEADS 16
#define DKK 64
#define BHS (BBATCH*HHEADS*SSEQ)

// Scratch (all fp16, fragment-interleaved for single-LDS.128 operand fetch)
__device__ unsigned short g_xi[4096*1024];    // x: [m>>7][k>>6][(g*4+ks)32][lane32][comp4] b32 words
__device__ unsigned short g_wi[3][1024*1024]; // W: [n>>7][k>>6][(ng*2+sp)32][lane32][comp4]
__device__ unsigned short g_k[BHS*DKK];       // K: [bh][tile64][(ng*2+sp)16][lane32][comp4]
__device__ unsigned short g_v[BHS*DKK];       // V: [bh][tile64][(dn*2+kcp)16][lane32][comp4]
__device__ unsigned short g_q[BHS*DKK];       // Q: natural [bh][s][d]  (carries 0.125*log2e)

// ---------------- helpers ----------------
__device__ __forceinline__ void mma16(float* d, uint32_t a0, uint32_t a1,
                                      uint32_t a2, uint32_t a3,
                                      uint32_t b0, uint32_t b1)
{
    asm volatile("mma.sync.aligned.m16n8k16.row.col.f32.f16.f16.f32 "
        "{%0,%1,%2,%3}, {%4,%5,%6,%7}, {%8,%9}, {%0,%1,%2,%3};"
        : "+f"(d[0]), "+f"(d[1]), "+f"(d[2]), "+f"(d[3])
        : "r"(a0), "r"(a1), "r"(a2), "r"(a3), "r"(b0), "r"(b1));
}
__device__ __forceinline__ void mma16v(float* d, const uint4& a, uint32_t b0, uint32_t b1){
    mma16(d, a.x, a.y, a.z, a.w, b0, b1);
}
__device__ __forceinline__ float ex2f(float x){
    float r; asm("ex2.approx.f32 %0, %1;" : "=f"(r) : "f"(x)); return r;
}
__device__ __forceinline__ uint32_t packh2(float a, float b){
    __half2 h = __floats2half2_rn(a, b);
    return *(uint32_t*)&h;
}
__device__ __forceinline__ uint32_t smem_u32(const void* p){
    uint32_t a;
    asm("{ .reg .u64 t; cvta.to.shared.u64 t, %1; cvt.u32.u64 %0, t; }" : "=r"(a) : "l"(p));
    return a;
}

#define MBAR_INIT(a, c) asm volatile("mbarrier.init.shared.b64 [%0], %1;" :: "r"(a), "r"(c) : "memory")
#define MBAR_EXPECT(a, bytes) \
    asm volatile("mbarrier.arrive.expect_tx.shared.b64 _, [%0], %1;" :: "r"(a), "r"(bytes) : "memory")
#define BULK_G2S(dst, src, bytes, mbar) \
    asm volatile("cp.async.bulk.shared::cta.global.mbarrier::complete_tx::bytes [%0], [%1], %2, [%3];" \
        :: "r"(dst), "l"(src), "r"(bytes), "r"(mbar) : "memory")

#define MBAR_WAIT(mbar, par) do {                                            \
    uint32_t _m = (mbar); uint32_t _p = (par); uint32_t _done;               \
    asm volatile("{ .reg .pred p; mbarrier.try_wait.parity.acquire.cta.shared::cta.b64 p, [%1], %2; selp.b32 %0,1,0,p; }" \
        : "=r"(_done) : "r"(_m), "r"(_p) : "memory");                        \
    if (!_done) {                                                            \
        asm volatile("{ .reg .pred P1; WL%=: mbarrier.try_wait.parity.acquire.cta.shared::cta.b64 P1, [%0], %1, 0x989680; @P1 bra.uni WD%=; bra.uni WL%=; WD%=: }" \
            :: "r"(_m), "r"(_p) : "memory");                                 \
    }                                                                        \
} while(0)

// =====================================================================
// Prep (DEST-MAJOR): each thread writes one uint4 (4 consecutive words)
// and gathers its 4 float2 sources. Layout byte-identical to R11/R13.
// =====================================================================
__global__ __launch_bounds__(256)
void prep_kernel(const float* __restrict__ x, const float* __restrict__ Wk,
                 const float* __restrict__ Wv, const float* __restrict__ Wq)
{
    const int t = blockIdx.x * 256 + threadIdx.x;
    if (blockIdx.y == 0) {
        // x: t = ((rb*16+ch)*32 + g*4+ks)*32 + gid*4+tig   (524288 threads)
        int l5 = t & 31, gid = l5 >> 2, tig = l5 & 3;
        int blk = t >> 5;
        int g = (blk & 31) >> 2, ks = blk & 3;
        int rbch = blk >> 5, ch = rbch & 15, rb = rbch >> 4;
        int mb = rb * 128 + g * 16 + gid;
        int kb = ch * 64 + ks * 16 + tig * 2;
        const float* xr0 = x + (size_t)mb * EEMB + kb;
        const float* xr8 = xr0 + 8 * EEMB;
        float2 a0 = *(const float2*)(xr0);       // (m,   k), (m,   k+1)
        float2 a1 = *(const float2*)(xr8);       // (m+8, k) ...
        float2 a2 = *(const float2*)(xr0 + 8);   // (m,   k+8)
        float2 a3 = *(const float2*)(xr8 + 8);
        uint4 w;
        w.x = packh2(a0.x, a0.y);
        w.y = packh2(a1.x, a1.y);
        w.z = packh2(a2.x, a2.y);
        w.w = packh2(a3.x, a3.y);
        *(uint4*)((uint32_t*)g_xi + (size_t)t * 4) = w;   // wait, g_xi is u16: word w at u16 idx 2w
    } else {
        // W: t = ((nb*16+ch)*32 + ng*2+sp)*32 + gid*4+tig   (131072 threads)
        if (t >= 131072) return;
        const float* W = (blockIdx.y == 1) ? Wk : (blockIdx.y == 2) ? Wv : Wq;
        unsigned short* dst = g_wi[blockIdx.y - 1];
        int l5 = t & 31, gid = l5 >> 2, tig = l5 & 3;
        int blk = t >> 5;
        int ng = (blk & 31) >> 1, sp = blk & 1;
        int nbch = blk >> 5, ch = nbch & 15, nb = nbch >> 4;
        int n = nb * 128 + ng * 8 + gid;
        int kbase = ch * 64 + sp * 32 + tig * 2;
        const float* wr = W + (size_t)n * EEMB + kbase;
        float2 b0 = *(const float2*)(wr);        // comp0: k+0
        float2 b1 = *(const float2*)(wr + 8);    // comp1: k+8
        float2 b2 = *(const float2*)(wr + 16);   // comp2: k+16
        float2 b3 = *(const float2*)(wr + 24);   // comp3: k+24
        uint4 w;
        w.x = packh2(b0.x, b0.y);
        w.y = packh2(b1.x, b1.y);
        w.z = packh2(b2.x, b2.y);
        w.w = packh2(b3.x, b3.y);
        *(uint4*)((uint32_t*)dst + (size_t)t * 4) = w;
    }
}

// =====================================================================
// Merged projection: fp16 m16n8k16, 16 chunks of 64k, 3-stage bulk.
// Epilogue: K, Q stores paired (u32); V paired via shfl_xor(4) (u32).
// =====================================================================
#define PJ_SMEM (98304 + 32)

__global__ __launch_bounds__(256, 2)
void proj_mma(const float* __restrict__ theta)
{
    extern __shared__ char smc[];
    const uint32_t sb = smem_u32(smc);
    const uint32_t mb0 = sb + 98304;
    const int tid = threadIdx.x;
    const int wid = tid >> 5, lane = tid & 31;
    const int gid = lane >> 2, tig = lane & 3;
    const int wm = wid >> 1, wn = wid & 1;
    const int row0 = blockIdx.y * 128;
    const int col0g = blockIdx.x * 128;
    const int mode = col0g >> 10;
    const int coll = col0g & 1023;
    const int nb = coll >> 7;

    float acc[2][8][4];
    #pragma unroll
    for (int i = 0; i < 2; i++)
        #pragma unroll
        for (int j = 0; j < 8; j++)
            #pragma unroll
            for (int e = 0; e < 4; e++) acc[i][j][e] = 0.f;

    const unsigned short* Ab = g_xi + (size_t)blockIdx.y * 131072;
    const unsigned short* Wb = g_wi[mode] + (size_t)nb * 131072;

    auto issue = [&](int ch, int b) {
        uint32_t mbar = mb0 + b * 8;
        MBAR_EXPECT(mbar, 32768u);
        BULK_G2S(sb + b * 16384,         (const void*)(Ab + ch * 8192), 16384u, mbar);
        BULK_G2S(sb + 49152 + b * 16384, (const void*)(Wb + ch * 8192), 16384u, mbar);
    };

    if (tid == 0) { MBAR_INIT(mb0, 1); MBAR_INIT(mb0 + 8, 1); MBAR_INIT(mb0 + 16, 1); }
    __syncthreads();
    if (tid == 0) { issue(0, 0); issue(1, 1); }

    int buf = 0, par = 0;
    #pragma unroll 1
    for (int ch = 0; ch < 16; ch++) {
        MBAR_WAIT(mb0 + buf * 8, par);
        __syncthreads();
        if (ch + 2 < 16 && tid == 0) {
            int nbuf = buf + 2; if (nbuf >= 3) nbuf -= 3;
            issue(ch + 2, nbuf);
        }

        const uint4* As = (const uint4*)(smc + buf * 16384);
        const uint4* Ws = (const uint4*)(smc + 49152 + buf * 16384);
        #pragma unroll
        for (int sp = 0; sp < 2; sp++) {
            uint4 af[2][2];
            #pragma unroll
            for (int tm = 0; tm < 2; tm++)
                #pragma unroll
                for (int kso = 0; kso < 2; kso++)
                    af[tm][kso] = As[((2*wm+tm)*4 + 2*sp+kso) * 32 + lane];
            #pragma unroll
            for (int tn = 0; tn < 8; tn++) {
                uint4 wb = Ws[((wn*8+tn)*2 + sp) * 32 + lane];
                #pragma unroll
                for (int tm = 0; tm < 2; tm++) {
                    mma16v(acc[tm][tn], af[tm][0], wb.x, wb.y);
                    mma16v(acc[tm][tn], af[tm][1], wb.z, wb.w);
                }
            }
        }
        if (++buf == 3) { buf = 0; par ^= 1; }
    }

    // ---- epilogue ----
    #pragma unroll
    for (int tm = 0; tm < 2; tm++) {
        #pragma unroll
        for (int tn = 0; tn < 8; tn++) {
            #pragma unroll
            for (int half = 0; half < 2; half++) {       // half 0: e0,e1 (row m); half 1: e2,e3 (row m+8)
                int m = row0 + wm * 32 + tm * 16 + gid + half * 8;
                int nn = coll + wn * 64 + tn * 8 + 2 * tig;    // even; pair covers nn, nn+1
                int b = m >> 11, s = m & (SSEQ - 1);
                int h = nn >> 6, d = nn & (DKK - 1);           // d even
                int bh = b * HHEADS + h;
                float v0 = acc[tm][tn][2 * half];
                float v1 = acc[tm][tn][2 * half + 1];
                if (mode == 0) {
                    // K: d,d+1 share one b-frag u32 word (kodd = 0/1)
                    int tile = s >> 6, key = s & 63;
                    int ng = key >> 3, gidk = key & 7;
                    int ks = d >> 4, sp = ks >> 1, kso = ks & 1;
                    int k16 = d & 15, khalf = k16 >> 3, tigk = (k16 & 7) >> 1;
                    int word = ((ng * 2 + sp) * 32 + gidk * 4 + tigk) * 4 + (kso * 2 + khalf);
                    uint32_t* dst32 = (uint32_t*)g_k;
                    dst32[(size_t)(bh * 32 + tile) * 2048 + word] = packh2(v0, v1);
                } else if (mode == 1) {
                    // V: word packs KEY pairs = adjacent gid = lanes xor 4.
                    float pv0 = __shfl_xor_sync(0xffffffffu, v0, 4);
                    float pv1 = __shfl_xor_sync(0xffffffffu, v1, 4);
                    if (!(gid & 1)) {
                        int tile = s >> 6, key = s & 63;       // key even here
                        int kc = key >> 4, kcp = kc >> 1, kco = kc & 1;
                        int key16 = key & 15, khalf = key16 >> 3, tigv = (key16 & 7) >> 1;
                        uint32_t* dst32 = (uint32_t*)g_v;
                        size_t base = (size_t)(bh * 32 + tile) * 2048;
                        int dn0 = d >> 3, gid0 = d & 7;
                        int w0 = ((dn0 * 2 + kcp) * 32 + gid0 * 4 + tigv) * 4 + (kco * 2 + khalf);
                        int d1 = d + 1, dn1 = d1 >> 3, gid1 = d1 & 7;
                        int w1 = ((dn1 * 2 + kcp) * 32 + gid1 * 4 + tigv) * 4 + (kco * 2 + khalf);
                        dst32[base + w0] = packh2(v0, pv0);
                        dst32[base + w1] = packh2(v1, pv1);
                    }
                } else {
                    // Q: natural layout, d and d+1 adjacent -> one u32 store (log2e folded)
                    float q0 = __cosf(v0 + __ldg(&theta[d]))     * 0.18033688011112042f;
                    float q1 = __cosf(v1 + __ldg(&theta[d + 1])) * 0.18033688011112042f;
                    uint32_t* dst32 = (uint32_t*)g_q;
                    dst32[(((size_t)bh * SSEQ + s) * DKK + d) >> 1] = packh2(q0, q1);
                }
            }
        }
    }
}

// =====================================================================
// Attention: R11/R13 structure (proven). CTA = 256q x 1 head, 8 warps.
// fp16 m16n8k16; P transpose free; ex2 with log2e pre-folded in Q.
// smem bytes: K[s] @ s*8192 ; V[s] @ 24576 + s*8192 ; mbars @ 49152
// =====================================================================
#define AT_SMEM (49152 + 32)

__global__ __launch_bounds__(256, 1)
void attn_mma(float* __restrict__ out)
{
    extern __shared__ char smc[];
    const uint32_t sb = smem_u32(smc);
    const uint32_t mb0 = sb + 49152;
    const int tid = threadIdx.x;
    const int wid = tid >> 5, lane = tid & 31;
    const int gid = lane >> 2, tig = lane & 3;
    const int bh = blockIdx.y;
    const int s0 = blockIdx.x * 256;

    // ---- Q fragments in registers: 2 m-groups x 4 k-steps ----
    uint4 qf[2][4];
    #pragma unroll
    for (int mg = 0; mg < 2; mg++) {
        const unsigned short* qb = g_q + ((size_t)bh * SSEQ + s0 + wid * 32 + mg * 16) * DKK;
        #pragma unroll
        for (int ks = 0; ks < 4; ks++) {
            int c = 16 * ks + 2 * tig;
            qf[mg][ks].x = *(const uint32_t*)(qb + gid * DKK + c);
            qf[mg][ks].y = *(const uint32_t*)(qb + (gid + 8) * DKK + c);
            qf[mg][ks].z = *(const uint32_t*)(qb + gid * DKK + c + 8);
            qf[mg][ks].w = *(const uint32_t*)(qb + (gid + 8) * DKK + c + 8);
        }
    }

    const unsigned short* kg = g_k + (size_t)bh * 131072;
    const unsigned short* vg = g_v + (size_t)bh * 131072;

    auto issue = [&](int t, int b) {
        uint32_t mbar = mb0 + b * 8;
        MBAR_EXPECT(mbar, 16384u);
        BULK_G2S(sb + b * 8192,         (const void*)(kg + t * 4096), 8192u, mbar);
        BULK_G2S(sb + 24576 + b * 8192, (const void*)(vg + t * 4096), 8192u, mbar);
    };

    if (tid == 0) { MBAR_INIT(mb0, 1); MBAR_INIT(mb0 + 8, 1); MBAR_INIT(mb0 + 16, 1); }
    __syncthreads();
    if (tid == 0) { issue(0, 0); issue(1, 1); }

    float oacc[2][8][4];
    #pragma unroll
    for (int mg = 0; mg < 2; mg++)
        #pragma unroll
        for (int dn = 0; dn < 8; dn++)
            #pragma unroll
            for (int e = 0; e < 4; e++) oacc[mg][dn][e] = 0.f;
    float lsum[2][2] = {{0.f, 0.f}, {0.f, 0.f}};

    int buf = 0, par = 0;
    #pragma unroll 1
    for (int t = 0; t < 32; t++) {
        MBAR_WAIT(mb0 + buf * 8, par);
        __syncthreads();
        if (t + 2 < 32 && tid == 0) {
            int nbuf = buf + 2; if (nbuf >= 3) nbuf -= 3;
            issue(t + 2, nbuf);
        }

        const uint4* Kp = (const uint4*)(smc + buf * 8192);
        const uint4* Vp = (const uint4*)(smc + 24576 + buf * 8192);

        // ---- S = Q @ K^T ----
        float sacc[2][8][4];
        #pragma unroll
        for (int mg = 0; mg < 2; mg++)
            #pragma unroll
            for (int tn = 0; tn < 8; tn++)
                #pragma unroll
                for (int e = 0; e < 4; e++) sacc[mg][tn][e] = 0.f;

        #pragma unroll
        for (int sp = 0; sp < 2; sp++) {
            #pragma unroll
            for (int tn = 0; tn < 8; tn++) {
                uint4 kb = Kp[(tn * 2 + sp) * 32 + lane];
                #pragma unroll
                for (int mg = 0; mg < 2; mg++) {
                    mma16v(sacc[mg][tn], qf[mg][2 * sp    ], kb.x, kb.y);
                    mma16v(sacc[mg][tn], qf[mg][2 * sp + 1], kb.z, kb.w);
                }
            }
        }

        // ---- P = ex2(S) (log2e folded into Q), row sums, pack fp16 ----
        uint32_t plo[2][8], phi[2][8];
        #pragma unroll
        for (int mg = 0; mg < 2; mg++)
            #pragma unroll
            for (int tn = 0; tn < 8; tn++) {
                float p0 = ex2f(sacc[mg][tn][0]);
                float p1 = ex2f(sacc[mg][tn][1]);
                float p2 = ex2f(sacc[mg][tn][2]);
                float p3 = ex2f(sacc[mg][tn][3]);
                lsum[mg][0] += p0 + p1;
                lsum[mg][1] += p2 + p3;
                plo[mg][tn] = packh2(p0, p1);
                phi[mg][tn] = packh2(p2, p3);
            }

        // ---- O += P @ V : A-frags directly from packed S pairs ----
        #pragma unroll
        for (int kcp = 0; kcp < 2; kcp++) {
            #pragma unroll
            for (int dn = 0; dn < 8; dn++) {
                uint4 vb = Vp[(dn * 2 + kcp) * 32 + lane];
                #pragma unroll
                for (int mg = 0; mg < 2; mg++) {
                    mma16(oacc[mg][dn],
                          plo[mg][4*kcp    ], phi[mg][4*kcp    ],
                          plo[mg][4*kcp + 1], phi[mg][4*kcp + 1],
                          vb.x, vb.y);
                    mma16(oacc[mg][dn],
                          plo[mg][4*kcp + 2], phi[mg][4*kcp + 2],
                          plo[mg][4*kcp + 3], phi[mg][4*kcp + 3],
                          vb.z, vb.w);
                }
            }
        }
        if (++buf == 3) { buf = 0; par ^= 1; }
    }

    // ---- finalize l (quad reduce) and write out ----
    #pragma unroll
    for (int mg = 0; mg < 2; mg++)
        #pragma unroll
        for (int r = 0; r < 2; r++) {
            lsum[mg][r] += __shfl_xor_sync(0xffffffffu, lsum[mg][r], 1);
            lsum[mg][r] += __shfl_xor_sync(0xffffffffu, lsum[mg][r], 2);
        }

    const int b = bh >> 4, h = bh & (HHEADS - 1);
    #pragma unroll
    for (int mg = 0; mg < 2; mg++) {
        const float inv0 = 1.f / lsum[mg][0];
        const float inv1 = 1.f / lsum[mg][1];
        float* o0 = out + ((size_t)b * SSEQ + s0 + wid * 32 + mg * 16 + gid) * EEMB + h * DKK;
        float* o1 = o0 + 8 * EEMB;
        #pragma unroll
        for (int dn = 0; dn < 8; dn++) {
            int c = dn * 8 + 2 * tig;
            *(float2*)(o0 + c) = make_float2(oacc[mg][dn][0] * inv0, oacc[mg][dn][1] * inv0);
            *(float2*)(o1 + c) = make_float2(oacc[mg][dn][2] * inv1, oacc[mg][dn][3] * inv1);
        }
    }
}

// ===================== launch =====================
extern "C" void kernel_launch(void* const* d_in, const int* in_sizes, int n_in,
                              void* d_out, int out_size)
{
    const float* x     = (const float*)d_in[0];
    const float* Wk    = (const float*)d_in[1];
    const float* Wv    = (const float*)d_in[2];
    const float* Wq    = (const float*)d_in[3];
    const float* theta = (const float*)d_in[4];
    float* out = (float*)d_out;

    cudaFuncSetAttribute(proj_mma, cudaFuncAttributeMaxDynamicSharedMemorySize, PJ_SMEM);
    cudaFuncSetAttribute(attn_mma, cudaFuncAttributeMaxDynamicSharedMemorySize, AT_SMEM);

    prep_kernel<<<dim3(2048, 4), 256>>>(x, Wk, Wv, Wq);

    dim3 gp(3 * EEMB / 128, (BBATCH * SSEQ) / 128);   // (24, 32)
    proj_mma<<<gp, 256, PJ_SMEM>>>(theta);

    dim3 ga(SSEQ / 256, BBATCH * HHEADS);              // (8, 32)
    attn_mma<<<ga, 256, AT_SMEM>>>(out);
}